// round 1
// baseline (speedup 1.0000x reference)
#include <cuda_runtime.h>

#define NB   8
#define NN   256
#define NIN  16
#define NH   32
#define TILE 16
#define NT   (NN/TILE)          // 16
#define NTRI (NT*(NT+1)/2)      // 136
#define NBLK2 (NB*NTRI)         // 1088

// ---- scratch (device globals; no runtime allocation allowed) ----
__device__ float g_h1[(size_t)NB*NN*NN*NH];   // 64 MB: layer-1 activations [b][i][j][s]
__device__ float g_R1[NB*NN*NH];
__device__ float g_Dg1[NB*NN*NH];
__device__ float g_T1[NB*NH];
__device__ float g_rowacc[NB*NN*NH];
__device__ float g_R2[NB*NN*NH];
__device__ float g_Dg2[NB*NN*NH];
__device__ float g_T2[NB*NH];
__device__ float g_part[(size_t)NBLK2*NH];

// ============================================================
// P1: per-batch precompute for layer 1.
//   S[d]     = sum_i x[i,d]
//   R1[i,s]  = (sum_{d<16} x[i,d]*W1[d,s,3] + sum_d' x[i,d']*S[d']*W1[16+d',s,3]) / n
//   Dg1[i,s] = sum_{d<16} x[i,d]*(W1[d,s,0]+W1[d,s,1]+W1[d,s,2]) + sum_d' x[i,d']^2*W1[16+d',s,2]
//   T1[s]    = b1[s] + sum_{d<16} S[d]/n^2*W1[d,s,4] + sum_d' S[d']^2/n^2*W1[16+d',s,4]
// ============================================================
__global__ void __launch_bounds__(256) p1_kernel(const float* __restrict__ x,
                                                 const float* __restrict__ W1,
                                                 const float* __restrict__ b1) {
    int b = blockIdx.x, tid = threadIdx.x;
    __shared__ float xs[NN*NIN];
    __shared__ float Ws[NH*NH*5];
    __shared__ float Ss[NIN];
    __shared__ float red[8*NIN];

    const float4* xg = (const float4*)(x + (size_t)b*NN*NIN);
    float4* xs4 = (float4*)xs;
    for (int e = tid; e < NN*NIN/4; e += 256) xs4[e] = xg[e];
    for (int e = tid; e < NH*NH*5; e += 256) Ws[e] = W1[e];
    __syncthreads();

    float xv[NIN];
    #pragma unroll
    for (int d = 0; d < NIN; d++) xv[d] = xs[tid*NIN + d];

    int lane = tid & 31, w = tid >> 5;
    #pragma unroll
    for (int d = 0; d < NIN; d++) {
        float v = xv[d];
        #pragma unroll
        for (int o = 16; o; o >>= 1) v += __shfl_xor_sync(0xffffffffu, v, o);
        if (lane == 0) red[w*NIN + d] = v;
    }
    __syncthreads();
    if (tid < NIN) {
        float s = 0.f;
        #pragma unroll
        for (int w2 = 0; w2 < 8; w2++) s += red[w2*NIN + tid];
        Ss[tid] = s;
    }
    __syncthreads();

    const float inv_n = 1.0f/(float)NN, inv_n2 = inv_n*inv_n;
    int i = tid;
    float x2v[NIN];
    #pragma unroll
    for (int d = 0; d < NIN; d++) x2v[d] = xv[d]*xv[d];

    for (int s = 0; s < NH; s++) {
        float r = 0.f, dg = 0.f;
        #pragma unroll
        for (int d = 0; d < NIN; d++) {
            const float* wd  = &Ws[(d*NH + s)*5];
            const float* wd2 = &Ws[((NIN+d)*NH + s)*5];
            r  += xv[d]*wd[3];
            r  += xv[d]*Ss[d]*wd2[3];
            dg += xv[d]*(wd[0] + wd[1] + wd[2]);
            dg += x2v[d]*wd2[2];
        }
        g_R1 [((size_t)b*NN + i)*NH + s] = r*inv_n;
        g_Dg1[((size_t)b*NN + i)*NH + s] = dg;
    }
    if (tid < NH) {
        int s = tid;
        float t = b1[s];
        #pragma unroll
        for (int d = 0; d < NIN; d++) {
            t += Ss[d]*inv_n2      * Ws[(d*NH + s)*5 + 4];
            t += Ss[d]*Ss[d]*inv_n2 * Ws[((NIN+d)*NH + s)*5 + 4];
        }
        g_T1[b*NH + s] = t;
    }
}

// ============================================================
// K1: h1[b,i,j,s] = relu( sum_d' x[i,d']x[j,d']*Wa[d',s] + R1 + T1 + diag )
// also rowacc[b,i,s] = sum_j h1
// grid (NN, NB), block 256 (thread = j)
// ============================================================
__global__ void __launch_bounds__(256) k1_kernel(const float* __restrict__ x,
                                                 const float* __restrict__ W1) {
    int i = blockIdx.x, b = blockIdx.y, j = threadIdx.x;
    __shared__ float xs[NN*NIN];
    __shared__ float Wa[NIN*NH];
    __shared__ float r1s[NH], t1s[NH], dg1s[NH];
    __shared__ float red[8*NH];

    const float4* xg = (const float4*)(x + (size_t)b*NN*NIN);
    float4* xs4 = (float4*)xs;
    for (int e = j; e < NN*NIN/4; e += 256) xs4[e] = xg[e];
    for (int e = j; e < NIN*NH; e += 256) {
        int dd = e >> 5, s = e & 31;
        const float* wq = W1 + ((NIN+dd)*NH + s)*5;
        Wa[e] = wq[0] + wq[1];           // symmetric h0: W0+W1 merge
    }
    if (j < NH) {
        r1s[j]  = g_R1 [((size_t)b*NN + i)*NH + j];
        dg1s[j] = g_Dg1[((size_t)b*NN + i)*NH + j];
        t1s[j]  = g_T1[b*NH + j];
    }
    __syncthreads();

    float z[NIN];
    #pragma unroll
    for (int d = 0; d < NIN; d++) z[d] = xs[i*NIN + d] * xs[j*NIN + d];

    float acc[NH];
    #pragma unroll
    for (int s = 0; s < NH; s++) acc[s] = r1s[s] + t1s[s];
    if (i == j) {
        #pragma unroll
        for (int s = 0; s < NH; s++) acc[s] += dg1s[s];
    }
    #pragma unroll
    for (int d = 0; d < NIN; d++) {
        float zd = z[d];
        #pragma unroll
        for (int s = 0; s < NH; s++) acc[s] = fmaf(zd, Wa[d*NH + s], acc[s]);
    }
    #pragma unroll
    for (int s = 0; s < NH; s++) acc[s] = fmaxf(acc[s], 0.f);

    float4* o4 = (float4*)(g_h1 + (((size_t)b*NN + i)*NN + j)*NH);
    #pragma unroll
    for (int k = 0; k < 8; k++)
        o4[k] = make_float4(acc[4*k], acc[4*k+1], acc[4*k+2], acc[4*k+3]);

    // row sums over j
    int lane = j & 31, w = j >> 5;
    #pragma unroll
    for (int s = 0; s < NH; s++) {
        float v = acc[s];
        #pragma unroll
        for (int o = 16; o; o >>= 1) v += __shfl_xor_sync(0xffffffffu, v, o);
        if (lane == 0) red[w*NH + s] = v;
    }
    __syncthreads();
    if (j < NH) {
        float t = 0.f;
        #pragma unroll
        for (int w2 = 0; w2 < 8; w2++) t += red[w2*NH + j];
        g_rowacc[((size_t)b*NN + i)*NH + j] = t;
    }
}

// ============================================================
// P2: layer-2 positional precomputes from h1 aggregates.
// ============================================================
__global__ void __launch_bounds__(256) p2_kernel(const float* __restrict__ W2,
                                                 const float* __restrict__ b2) {
    int b = blockIdx.x, tid = threadIdx.x;
    __shared__ float Ws[NH*NH*5];
    __shared__ float red[8*NH];
    __shared__ float tot[NH];
    for (int e = tid; e < NH*NH*5; e += 256) Ws[e] = W2[e];

    float ra[NH], dv[NH];
    const float* rp = g_rowacc + ((size_t)b*NN + tid)*NH;
    const float* dp = g_h1 + (((size_t)b*NN + tid)*NN + tid)*NH;  // diag of h1
    #pragma unroll
    for (int t = 0; t < NH; t++) { ra[t] = rp[t]; dv[t] = dp[t]; }
    __syncthreads();

    int lane = tid & 31, w = tid >> 5;
    #pragma unroll
    for (int t = 0; t < NH; t++) {
        float v = ra[t];
        #pragma unroll
        for (int o = 16; o; o >>= 1) v += __shfl_xor_sync(0xffffffffu, v, o);
        if (lane == 0) red[w*NH + t] = v;
    }
    __syncthreads();
    if (tid < NH) {
        float s = 0.f;
        #pragma unroll
        for (int w2 = 0; w2 < 8; w2++) s += red[w2*NH + tid];
        tot[tid] = s * (1.0f/((float)NN*(float)NN));
    }
    __syncthreads();

    const float inv_n = 1.0f/(float)NN;
    for (int s = 0; s < NH; s++) {
        float r2 = 0.f, dg2 = 0.f;
        #pragma unroll
        for (int t = 0; t < NH; t++) {
            r2  = fmaf(ra[t]*inv_n, Ws[(t*NH + s)*5 + 3], r2);
            dg2 = fmaf(dv[t],       Ws[(t*NH + s)*5 + 2], dg2);
        }
        g_R2 [((size_t)b*NN + tid)*NH + s] = r2;
        g_Dg2[((size_t)b*NN + tid)*NH + s] = dg2;
    }
    if (tid < NH) {
        int s = tid;
        float t2 = b2[s];
        #pragma unroll
        for (int t = 0; t < NH; t++) t2 = fmaf(tot[t], Ws[(t*NH + s)*5 + 4], t2);
        g_T2[b*NH + s] = t2;
    }
}

// ============================================================
// K2: pooled partials. Upper-triangular 16x16 tile pairs; each thread
// computes element (i,j) AND (j,i) via Karatsuba sum/diff form.
// ============================================================
__global__ void __launch_bounds__(256, 2) k2_kernel(const float* __restrict__ W2) {
    extern __shared__ float sm[];
    float* As  = sm;                   // 256*33
    float* Bs  = As + 256*33;          // 256*33
    float* Wp  = Bs + 256*33;          // 32*32  (W0+W1)
    float* Wm  = Wp + NH*NH;           // 32*32  (W0-W1)
    float* red = Wm + NH*NH;           // 8*32

    int bid = blockIdx.x;
    int b = bid / NTRI;
    int t = bid % NTRI;
    int ti = 0;
    while (t >= NT - ti) { t -= NT - ti; ti++; }
    int tj = ti + t;
    int tid = threadIdx.x;

    for (int e = tid; e < NH*NH; e += 256) {
        float w0 = W2[e*5 + 0], w1 = W2[e*5 + 1];
        Wp[e] = w0 + w1; Wm[e] = w0 - w1;
    }

    int I = ti*TILE, J = tj*TILE;
    const float* h1b = g_h1 + (size_t)b*NN*NN*NH;
    #pragma unroll
    for (int k = 0; k < 8; k++) {
        int f = k*256 + tid;
        int p = f >> 3, sq = f & 7;
        int pi = p >> 4, pj = p & 15;
        float4 va = *(const float4*)(h1b + ((size_t)(I+pi)*NN + (J+pj))*NH + sq*4);
        int oa = p*33 + sq*4;
        As[oa] = va.x; As[oa+1] = va.y; As[oa+2] = va.z; As[oa+3] = va.w;
        // transposed tile: Bs[ii*16+jj] holds h1[J+jj, I+ii]
        float4 vb = *(const float4*)(h1b + ((size_t)(J+pi)*NN + (I+pj))*NH + sq*4);
        int q = (pj << 4) | pi;
        int ob = q*33 + sq*4;
        Bs[ob] = vb.x; Bs[ob+1] = vb.y; Bs[ob+2] = vb.z; Bs[ob+3] = vb.w;
    }
    __syncthreads();

    int ii = tid >> 4, jj = tid & 15;
    const float* av = As + tid*33;
    const float* bv = Bs + tid*33;

    float accP[NH], accM[NH];
    #pragma unroll
    for (int s = 0; s < NH; s++) { accP[s] = 0.f; accM[s] = 0.f; }

    #pragma unroll 4
    for (int tt = 0; tt < NH; tt++) {
        float vt = av[tt], ut = bv[tt];
        float ap = vt + ut, am = vt - ut;
        const float* wpr = Wp + tt*NH;
        const float* wmr = Wm + tt*NH;
        #pragma unroll
        for (int s = 0; s < NH; s++) {
            accP[s] = fmaf(ap, wpr[s], accP[s]);
            accM[s] = fmaf(am, wmr[s], accM[s]);
        }
    }

    bool isdiag = (ti == tj);
    const float* r2i = g_R2  + ((size_t)b*NN + I + ii)*NH;
    const float* r2j = g_R2  + ((size_t)b*NN + J + jj)*NH;
    const float* dgi = g_Dg2 + ((size_t)b*NN + I + ii)*NH;
    const float* t2  = g_T2  + b*NH;

    int lane = tid & 31, w = tid >> 5;
    #pragma unroll
    for (int s = 0; s < NH; s++) {
        float base1 = r2i[s] + t2[s];
        if (isdiag && ii == jj) base1 += dgi[s];
        float base2 = r2j[s] + t2[s];
        float a1 = 0.5f*(accP[s] + accM[s]) + base1;   // element (I+ii, J+jj)
        float a2 = 0.5f*(accP[s] - accM[s]) + base2;   // element (J+jj, I+ii)
        float c1 = fmaxf(a1, 0.f), c2 = fmaxf(a2, 0.f);
        float cs = c1 + c2;
        if (isdiag) cs = (ii < jj) ? (c1 + c2) : ((ii == jj) ? c1 : 0.f);
        #pragma unroll
        for (int o = 16; o; o >>= 1) cs += __shfl_xor_sync(0xffffffffu, cs, o);
        if (lane == 0) red[w*NH + s] = cs;
    }
    __syncthreads();
    if (tid < NH) {
        float p = 0.f;
        #pragma unroll
        for (int w2 = 0; w2 < 8; w2++) p += red[w2*NH + tid];
        g_part[(size_t)bid*NH + tid] = p;
    }
}

// ============================================================
// Final: deterministic partial reduce + relu + MLP 32->128->128->1
// ============================================================
__global__ void __launch_bounds__(128) fin_kernel(const float* __restrict__ D1,
                                                  const float* __restrict__ db1,
                                                  const float* __restrict__ D2,
                                                  const float* __restrict__ db2,
                                                  const float* __restrict__ D3,
                                                  const float* __restrict__ db3,
                                                  float* __restrict__ out) {
    int b = blockIdx.x, tid = threadIdx.x;
    __shared__ float p[NH];
    __shared__ float m1[128];
    __shared__ float m2[128];
    __shared__ float wr[4];

    if (tid < NH) {
        float s = 0.f;
        #pragma unroll 8
        for (int k = 0; k < NTRI; k++) s += g_part[(size_t)(b*NTRI + k)*NH + tid];
        p[tid] = fmaxf(s, 0.f);
    }
    __syncthreads();
    {
        float a = db1[tid];
        #pragma unroll
        for (int t = 0; t < NH; t++) a = fmaf(p[t], D1[t*128 + tid], a);
        m1[tid] = fmaxf(a, 0.f);
    }
    __syncthreads();
    {
        float a = db2[tid];
        #pragma unroll 8
        for (int e = 0; e < 128; e++) a = fmaf(m1[e], D2[e*128 + tid], a);
        m2[tid] = fmaxf(a, 0.f);
    }
    __syncthreads();
    float v = m2[tid] * D3[tid];
    #pragma unroll
    for (int o = 16; o; o >>= 1) v += __shfl_xor_sync(0xffffffffu, v, o);
    if ((tid & 31) == 0) wr[tid >> 5] = v;
    __syncthreads();
    if (tid == 0) out[b] = wr[0] + wr[1] + wr[2] + wr[3] + db3[0];
}

extern "C" void kernel_launch(void* const* d_in, const int* in_sizes, int n_in,
                              void* d_out, int out_size) {
    const float* x   = (const float*)d_in[0];
    const float* W1  = (const float*)d_in[1];
    const float* b1  = (const float*)d_in[2];
    const float* W2  = (const float*)d_in[3];
    const float* b2  = (const float*)d_in[4];
    const float* D1  = (const float*)d_in[5];
    const float* db1 = (const float*)d_in[6];
    const float* D2  = (const float*)d_in[7];
    const float* db2 = (const float*)d_in[8];
    const float* D3  = (const float*)d_in[9];
    const float* db3 = (const float*)d_in[10];
    float* out = (float*)d_out;

    size_t k2_smem = (size_t)(2*256*33 + 2*NH*NH + 8*NH) * sizeof(float);  // ~76.8 KB
    cudaFuncSetAttribute(k2_kernel, cudaFuncAttributeMaxDynamicSharedMemorySize,
                         (int)k2_smem);

    p1_kernel<<<NB, 256>>>(x, W1, b1);
    k1_kernel<<<dim3(NN, NB), 256>>>(x, W1);
    p2_kernel<<<NB, 256>>>(W2, b2);
    k2_kernel<<<NBLK2, 256, k2_smem>>>(W2);
    fin_kernel<<<NB, 128>>>(D1, db1, D2, db2, D3, db3, out);
}

// round 2
// speedup vs baseline: 1.0328x; 1.0328x over previous
#include <cuda_runtime.h>
#include <cuda_bf16.h>

#define NB   8
#define NN   256
#define NIN  16
#define NH   32
#define TILE 16
#define NT   (NN/TILE)          // 16
#define NTRI (NT*(NT+1)/2)      // 136
#define NBLK2 (NB*NTRI)         // 1088

typedef unsigned long long ull;

// ---- packed f32x2 helpers (FFMA2 path, PTX-only) ----
__device__ __forceinline__ ull packf2(float lo, float hi) {
    ull r; asm("mov.b64 %0, {%1, %2};" : "=l"(r) : "f"(lo), "f"(hi)); return r;
}
__device__ __forceinline__ ull packdup(float v) {
    ull r; asm("mov.b64 %0, {%1, %1};" : "=l"(r) : "f"(v)); return r;
}
__device__ __forceinline__ ull ffma2(ull a, ull b, ull c) {
    ull d; asm("fma.rn.f32x2 %0, %1, %2, %3;" : "=l"(d) : "l"(a), "l"(b), "l"(c)); return d;
}
__device__ __forceinline__ float2 unpackf2(ull v) {
    float lo, hi; asm("mov.b64 {%0, %1}, %2;" : "=f"(lo), "=f"(hi) : "l"(v));
    return make_float2(lo, hi);
}

// ---- scratch (device globals) ----
__device__ __nv_bfloat16 g_h1[(size_t)NB*NN*NN*NH];   // 32 MB, fits L2
__device__ float g_rowacc[NB*NN*NH];
__device__ float g_R2[NB*NN*NH];
__device__ float g_Dg2[NB*NN*NH];
__device__ float g_T2[NB*NH];
__device__ float g_part[(size_t)NBLK2*NH];

// ============================================================
// K1 (p1 folded in): h1[b,i,j,s] = relu( sum_d x[i,d]x[j,d]*Wa[d,s] + R1[i,s] + T1[s] + diag )
// rowacc[b,i,s] = sum_j h1. grid (NN, NB), block 256 (thread = j).
// ============================================================
__global__ void __launch_bounds__(256) k1_kernel(const float* __restrict__ x,
                                                 const float* __restrict__ W1,
                                                 const float* __restrict__ b1) {
    int i = blockIdx.x, b = blockIdx.y, j = threadIdx.x;
    __shared__ float xs[NN*NIN];
    __shared__ __align__(16) ull Wa2[NIN*16];   // packed (W0+W1) pairs over s
    __shared__ float Ss[NIN];
    __shared__ float r1s[NH], t1s[NH], dg1s[NH];
    __shared__ float red[8*NH];

    const float4* xg = (const float4*)(x + (size_t)b*NN*NIN);
    float4* xs4 = (float4*)xs;
    #pragma unroll
    for (int e = j; e < NN*NIN/4; e += 256) xs4[e] = xg[e];
    {
        int d = j >> 4, k = j & 15, s0 = 2*k;
        float a0 = W1[((NIN+d)*NH + s0  )*5 + 0] + W1[((NIN+d)*NH + s0  )*5 + 1];
        float a1 = W1[((NIN+d)*NH + s0+1)*5 + 0] + W1[((NIN+d)*NH + s0+1)*5 + 1];
        Wa2[j] = packf2(a0, a1);
    }
    __syncthreads();

    // column sums S[d] = sum_i x[i,d]
    {
        int lane = j & 31, w = j >> 5;
        #pragma unroll
        for (int d = 0; d < NIN; d++) {
            float v = xs[j*NIN + d];
            #pragma unroll
            for (int o = 16; o; o >>= 1) v += __shfl_xor_sync(0xffffffffu, v, o);
            if (lane == 0) red[w*NIN + d] = v;
        }
    }
    __syncthreads();
    if (j < NIN) {
        float s = 0.f;
        #pragma unroll
        for (int w2 = 0; w2 < 8; w2++) s += red[w2*NIN + j];
        Ss[j] = s;
    }
    __syncthreads();

    // per-row positional terms for row i (threads 0..31, one s each)
    if (j < NH) {
        const float inv_n = 1.0f/(float)NN, inv_n2 = inv_n*inv_n;
        int s = j; float r = 0.f, dg = 0.f, t = b1[s];
        #pragma unroll
        for (int d = 0; d < NIN; d++) {
            float xi = xs[i*NIN + d];
            const float* wd  = W1 + (d*NH + s)*5;
            const float* wd2 = W1 + ((NIN+d)*NH + s)*5;
            r  += xi*wd[3] + xi*Ss[d]*wd2[3];
            dg += xi*(wd[0] + wd[1] + wd[2]) + xi*xi*wd2[2];
            t  += Ss[d]*inv_n2*wd[4] + Ss[d]*Ss[d]*inv_n2*wd2[4];
        }
        r1s[s] = r*inv_n; dg1s[s] = dg; t1s[s] = t;
    }
    __syncthreads();

    float z[NIN];
    #pragma unroll
    for (int d = 0; d < NIN; d++) z[d] = xs[i*NIN + d] * xs[j*NIN + d];

    ull acc2[16];
    bool isdg = (i == j);
    #pragma unroll
    for (int k = 0; k < 16; k++) {
        float a0 = r1s[2*k] + t1s[2*k], a1 = r1s[2*k+1] + t1s[2*k+1];
        if (isdg) { a0 += dg1s[2*k]; a1 += dg1s[2*k+1]; }
        acc2[k] = packf2(a0, a1);
    }
    #pragma unroll
    for (int d = 0; d < NIN; d++) {
        ull zd = packdup(z[d]);
        const ulonglong2* w = (const ulonglong2*)(Wa2 + d*16);
        #pragma unroll
        for (int k4 = 0; k4 < 8; k4++) {
            ulonglong2 ww = w[k4];
            acc2[2*k4]   = ffma2(zd, ww.x, acc2[2*k4]);
            acc2[2*k4+1] = ffma2(zd, ww.y, acc2[2*k4+1]);
        }
    }
    float acc[NH];
    #pragma unroll
    for (int k = 0; k < 16; k++) {
        float2 f2 = unpackf2(acc2[k]);
        acc[2*k]   = fmaxf(f2.x, 0.f);
        acc[2*k+1] = fmaxf(f2.y, 0.f);
    }

    // store h1 row as bf16 (64B = 4x uint4)
    {
        unsigned int hx[16];
        #pragma unroll
        for (int k = 0; k < 16; k++) {
            __nv_bfloat162 h2 = __floats2bfloat162_rn(acc[2*k], acc[2*k+1]);
            hx[k] = *reinterpret_cast<unsigned int*>(&h2);
        }
        uint4* o4 = (uint4*)(g_h1 + (((size_t)b*NN + i)*NN + j)*NH);
        o4[0] = make_uint4(hx[0],  hx[1],  hx[2],  hx[3]);
        o4[1] = make_uint4(hx[4],  hx[5],  hx[6],  hx[7]);
        o4[2] = make_uint4(hx[8],  hx[9],  hx[10], hx[11]);
        o4[3] = make_uint4(hx[12], hx[13], hx[14], hx[15]);
    }

    // row sums over j (fp32, pre-quantization — fine, only final accuracy matters)
    int lane = j & 31, w = j >> 5;
    #pragma unroll
    for (int s = 0; s < NH; s++) {
        float v = acc[s];
        #pragma unroll
        for (int o = 16; o; o >>= 1) v += __shfl_xor_sync(0xffffffffu, v, o);
        if (lane == 0) red[w*NH + s] = v;
    }
    __syncthreads();
    if (j < NH) {
        float t = 0.f;
        #pragma unroll
        for (int w2 = 0; w2 < 8; w2++) t += red[w2*NH + j];
        g_rowacc[((size_t)b*NN + i)*NH + j] = t;
    }
}

// ============================================================
// P2: layer-2 positional precomputes from h1 aggregates.
// ============================================================
__global__ void __launch_bounds__(256) p2_kernel(const float* __restrict__ W2,
                                                 const float* __restrict__ b2) {
    int b = blockIdx.x, tid = threadIdx.x;
    __shared__ float Ws[NH*NH*5];
    __shared__ float red[8*NH];
    __shared__ float tot[NH];
    for (int e = tid; e < NH*NH*5; e += 256) Ws[e] = W2[e];

    float ra[NH], dv[NH];
    const float* rp = g_rowacc + ((size_t)b*NN + tid)*NH;
    const __nv_bfloat16* dp = g_h1 + (((size_t)b*NN + tid)*NN + tid)*NH;
    #pragma unroll
    for (int t = 0; t < NH; t++) { ra[t] = rp[t]; dv[t] = __bfloat162float(dp[t]); }
    __syncthreads();

    int lane = tid & 31, w = tid >> 5;
    #pragma unroll
    for (int t = 0; t < NH; t++) {
        float v = ra[t];
        #pragma unroll
        for (int o = 16; o; o >>= 1) v += __shfl_xor_sync(0xffffffffu, v, o);
        if (lane == 0) red[w*NH + t] = v;
    }
    __syncthreads();
    if (tid < NH) {
        float s = 0.f;
        #pragma unroll
        for (int w2 = 0; w2 < 8; w2++) s += red[w2*NH + tid];
        tot[tid] = s * (1.0f/((float)NN*(float)NN));
    }
    __syncthreads();

    const float inv_n = 1.0f/(float)NN;
    for (int s = 0; s < NH; s++) {
        float r2 = 0.f, dg2 = 0.f;
        #pragma unroll
        for (int t = 0; t < NH; t++) {
            r2  = fmaf(ra[t]*inv_n, Ws[(t*NH + s)*5 + 3], r2);
            dg2 = fmaf(dv[t],       Ws[(t*NH + s)*5 + 2], dg2);
        }
        g_R2 [((size_t)b*NN + tid)*NH + s] = r2;
        g_Dg2[((size_t)b*NN + tid)*NH + s] = dg2;
    }
    if (tid < NH) {
        int s = tid;
        float t2 = b2[s];
        #pragma unroll
        for (int t = 0; t < NH; t++) t2 = fmaf(tot[t], Ws[(t*NH + s)*5 + 4], t2);
        g_T2[b*NH + s] = t2;
    }
}

// ============================================================
// K2: pooled partials. Karatsuba pair form, f32x2 FMAs, vectorized W LDS.
// ============================================================
__global__ void __launch_bounds__(256, 2) k2_kernel(const float* __restrict__ W2) {
    extern __shared__ char smraw[];
    ull*   Wp2 = (ull*)smraw;            // 32*16 packed (W0+W1) pairs
    ull*   Wm2 = Wp2 + NH*16;            // 32*16 packed (W0-W1) pairs
    float* As  = (float*)(Wm2 + NH*16);  // 256*33
    float* Bs  = As + 256*33;            // 256*33
    float* red = Bs + 256*33;            // 8*32

    int bid = blockIdx.x;
    int b = bid / NTRI;
    int t = bid % NTRI;
    int ti = 0;
    while (t >= NT - ti) { t -= NT - ti; ti++; }
    int tj = ti + t;
    int tid = threadIdx.x;

    for (int e = tid; e < NH*16; e += 256) {
        int tt = e >> 4, k = e & 15, s0 = 2*k;
        float w00 = W2[(tt*NH + s0  )*5 + 0], w01 = W2[(tt*NH + s0  )*5 + 1];
        float w10 = W2[(tt*NH + s0+1)*5 + 0], w11 = W2[(tt*NH + s0+1)*5 + 1];
        Wp2[e] = packf2(w00 + w01, w10 + w11);
        Wm2[e] = packf2(w00 - w01, w10 - w11);
    }

    int I = ti*TILE, J = tj*TILE;
    const __nv_bfloat16* h1b = g_h1 + (size_t)b*NN*NN*NH;
    #pragma unroll
    for (int k = 0; k < 4; k++) {
        int f = k*256 + tid;
        int p = f >> 2, sq = f & 3;
        int pi = p >> 4, pj = p & 15;
        uint4 va = *(const uint4*)(h1b + ((size_t)(I+pi)*NN + (J+pj))*NH + sq*8);
        {
            float* dst = As + p*33 + sq*8;
            unsigned int vs[4] = {va.x, va.y, va.z, va.w};
            #pragma unroll
            for (int w = 0; w < 4; w++) {
                float2 f2 = __bfloat1622float2(*(const __nv_bfloat162*)&vs[w]);
                dst[2*w] = f2.x; dst[2*w+1] = f2.y;
            }
        }
        uint4 vb = *(const uint4*)(h1b + ((size_t)(J+pi)*NN + (I+pj))*NH + sq*8);
        {
            int q = (pj << 4) | pi;                 // transposed tile
            float* dst = Bs + q*33 + sq*8;
            unsigned int vs[4] = {vb.x, vb.y, vb.z, vb.w};
            #pragma unroll
            for (int w = 0; w < 4; w++) {
                float2 f2 = __bfloat1622float2(*(const __nv_bfloat162*)&vs[w]);
                dst[2*w] = f2.x; dst[2*w+1] = f2.y;
            }
        }
    }
    __syncthreads();

    int ii = tid >> 4, jj = tid & 15;
    const float* av = As + tid*33;
    const float* bv = Bs + tid*33;

    ull accP2[16], accM2[16];
    #pragma unroll
    for (int k = 0; k < 16; k++) { accP2[k] = 0ull; accM2[k] = 0ull; }

    #pragma unroll 4
    for (int tt = 0; tt < NH; tt++) {
        float vt = av[tt], ut = bv[tt];
        ull ap2 = packdup(vt + ut);
        ull am2 = packdup(vt - ut);
        const ulonglong2* wp = (const ulonglong2*)(Wp2 + tt*16);
        const ulonglong2* wm = (const ulonglong2*)(Wm2 + tt*16);
        #pragma unroll
        for (int k4 = 0; k4 < 8; k4++) {
            ulonglong2 wwp = wp[k4];
            accP2[2*k4]   = ffma2(ap2, wwp.x, accP2[2*k4]);
            accP2[2*k4+1] = ffma2(ap2, wwp.y, accP2[2*k4+1]);
            ulonglong2 wwm = wm[k4];
            accM2[2*k4]   = ffma2(am2, wwm.x, accM2[2*k4]);
            accM2[2*k4+1] = ffma2(am2, wwm.y, accM2[2*k4+1]);
        }
    }

    float accP[NH], accM[NH];
    #pragma unroll
    for (int k = 0; k < 16; k++) {
        float2 p2 = unpackf2(accP2[k]); accP[2*k] = p2.x; accP[2*k+1] = p2.y;
        float2 m2 = unpackf2(accM2[k]); accM[2*k] = m2.x; accM[2*k+1] = m2.y;
    }

    bool isdiag = (ti == tj);
    const float* r2i = g_R2  + ((size_t)b*NN + I + ii)*NH;
    const float* r2j = g_R2  + ((size_t)b*NN + J + jj)*NH;
    const float* dgi = g_Dg2 + ((size_t)b*NN + I + ii)*NH;
    const float* t2  = g_T2  + b*NH;

    int lane = tid & 31, w = tid >> 5;
    #pragma unroll
    for (int s = 0; s < NH; s++) {
        float base1 = r2i[s] + t2[s];
        if (isdiag && ii == jj) base1 += dgi[s];
        float base2 = r2j[s] + t2[s];
        float a1 = 0.5f*(accP[s] + accM[s]) + base1;   // element (I+ii, J+jj)
        float a2 = 0.5f*(accP[s] - accM[s]) + base2;   // element (J+jj, I+ii)
        float c1 = fmaxf(a1, 0.f), c2 = fmaxf(a2, 0.f);
        float cs = c1 + c2;
        if (isdiag) cs = (ii < jj) ? (c1 + c2) : ((ii == jj) ? c1 : 0.f);
        #pragma unroll
        for (int o = 16; o; o >>= 1) cs += __shfl_xor_sync(0xffffffffu, cs, o);
        if (lane == 0) red[w*NH + s] = cs;
    }
    __syncthreads();
    if (tid < NH) {
        float p = 0.f;
        #pragma unroll
        for (int w2 = 0; w2 < 8; w2++) p += red[w2*NH + tid];
        g_part[(size_t)bid*NH + tid] = p;
    }
}

// ============================================================
// Final: partial reduce + relu + MLP 32->128->128->1
// ============================================================
__global__ void __launch_bounds__(128) fin_kernel(const float* __restrict__ D1,
                                                  const float* __restrict__ db1,
                                                  const float* __restrict__ D2,
                                                  const float* __restrict__ db2,
                                                  const float* __restrict__ D3,
                                                  const float* __restrict__ db3,
                                                  float* __restrict__ out) {
    int b = blockIdx.x, tid = threadIdx.x;
    __shared__ float p[NH];
    __shared__ float m1[128];
    __shared__ float m2[128];
    __shared__ float wr[4];

    if (tid < NH) {
        float s = 0.f;
        #pragma unroll 8
        for (int k = 0; k < NTRI; k++) s += g_part[(size_t)(b*NTRI + k)*NH + tid];
        p[tid] = fmaxf(s, 0.f);
    }
    __syncthreads();
    {
        float a = db1[tid];
        #pragma unroll
        for (int t = 0; t < NH; t++) a = fmaf(p[t], D1[t*128 + tid], a);
        m1[tid] = fmaxf(a, 0.f);
    }
    __syncthreads();
    {
        float a = db2[tid];
        #pragma unroll 8
        for (int e = 0; e < 128; e++) a = fmaf(m1[e], D2[e*128 + tid], a);
        m2[tid] = fmaxf(a, 0.f);
    }
    __syncthreads();
    float v = m2[tid] * D3[tid];
    #pragma unroll
    for (int o = 16; o; o >>= 1) v += __shfl_xor_sync(0xffffffffu, v, o);
    if ((tid & 31) == 0) wr[tid >> 5] = v;
    __syncthreads();
    if (tid == 0) out[b] = wr[0] + wr[1] + wr[2] + wr[3] + db3[0];
}

extern "C" void kernel_launch(void* const* d_in, const int* in_sizes, int n_in,
                              void* d_out, int out_size) {
    const float* x   = (const float*)d_in[0];
    const float* W1  = (const float*)d_in[1];
    const float* b1  = (const float*)d_in[2];
    const float* W2  = (const float*)d_in[3];
    const float* b2  = (const float*)d_in[4];
    const float* D1  = (const float*)d_in[5];
    const float* db1 = (const float*)d_in[6];
    const float* D2  = (const float*)d_in[7];
    const float* db2 = (const float*)d_in[8];
    const float* D3  = (const float*)d_in[9];
    const float* db3 = (const float*)d_in[10];
    float* out = (float*)d_out;

    size_t k2_smem = (size_t)(2*NH*16*8) + (size_t)(2*256*33 + 8*NH)*4;  // 76800 B
    cudaFuncSetAttribute(k2_kernel, cudaFuncAttributeMaxDynamicSharedMemorySize,
                         (int)k2_smem);

    k1_kernel<<<dim3(NN, NB), 256>>>(x, W1, b1);
    p2_kernel<<<NB, 256>>>(W2, b2);
    k2_kernel<<<NBLK2, 256, k2_smem>>>(W2);
    fin_kernel<<<NB, 128>>>(D1, db1, D2, db2, D3, db3, out);
}

// round 3
// speedup vs baseline: 1.1877x; 1.1500x over previous
#include <cuda_runtime.h>
#include <cuda_bf16.h>

#define NB   8
#define NN   256
#define NIN  16
#define NH   32
#define TILE 16
#define NT   (NN/TILE)          // 16
#define NTRI (NT*(NT+1)/2)      // 136
#define NBLK2 (NB*NTRI)         // 1088

typedef unsigned long long ull;

// ---- packed f32x2 helpers ----
__device__ __forceinline__ ull packf2(float lo, float hi) {
    ull r; asm("mov.b64 %0, {%1, %2};" : "=l"(r) : "f"(lo), "f"(hi)); return r;
}
__device__ __forceinline__ ull packdup(float v) {
    ull r; asm("mov.b64 %0, {%1, %1};" : "=l"(r) : "f"(v)); return r;
}
__device__ __forceinline__ ull ffma2(ull a, ull b, ull c) {
    ull d; asm("fma.rn.f32x2 %0, %1, %2, %3;" : "=l"(d) : "l"(a), "l"(b), "l"(c)); return d;
}
__device__ __forceinline__ float2 unpackf2(ull v) {
    float lo, hi; asm("mov.b64 {%0, %1}, %2;" : "=f"(lo), "=f"(hi) : "l"(v));
    return make_float2(lo, hi);
}

// ---- scratch (device globals) ----
__device__ __nv_bfloat16 g_h1[(size_t)NB*NN*NN*NH];   // 32 MB
__device__ float g_R1[NB*NN*NH];
__device__ float g_Dg1[NB*NN*NH];
__device__ float g_T1[NB*NH];
__device__ float g_rowacc[NB*NN*NH];
__device__ float g_R2[NB*NN*NH];
__device__ float g_Dg2[NB*NN*NH];
__device__ float g_T2[NB*NH];
__device__ float g_part[(size_t)NBLK2*NH];

// ============================================================
// P1: per-batch positional precompute for layer 1 (8 blocks).
// ============================================================
__global__ void __launch_bounds__(256) p1_kernel(const float* __restrict__ x,
                                                 const float* __restrict__ W1,
                                                 const float* __restrict__ b1) {
    int b = blockIdx.x, tid = threadIdx.x;
    __shared__ float xs[NN*NIN];
    __shared__ float Ws[NH*NH*5];
    __shared__ float Ss[NIN];
    __shared__ float red[8*NIN];

    const float4* xg = (const float4*)(x + (size_t)b*NN*NIN);
    float4* xs4 = (float4*)xs;
    for (int e = tid; e < NN*NIN/4; e += 256) xs4[e] = xg[e];
    for (int e = tid; e < NH*NH*5; e += 256) Ws[e] = W1[e];
    __syncthreads();

    float xv[NIN];
    #pragma unroll
    for (int d = 0; d < NIN; d++) xv[d] = xs[tid*NIN + d];

    int lane = tid & 31, w = tid >> 5;
    #pragma unroll
    for (int d = 0; d < NIN; d++) {
        float v = xv[d];
        #pragma unroll
        for (int o = 16; o; o >>= 1) v += __shfl_xor_sync(0xffffffffu, v, o);
        if (lane == 0) red[w*NIN + d] = v;
    }
    __syncthreads();
    if (tid < NIN) {
        float s = 0.f;
        #pragma unroll
        for (int w2 = 0; w2 < 8; w2++) s += red[w2*NIN + tid];
        Ss[tid] = s;
    }
    __syncthreads();

    const float inv_n = 1.0f/(float)NN, inv_n2 = inv_n*inv_n;
    int i = tid;
    for (int s = 0; s < NH; s++) {
        float r = 0.f, dg = 0.f;
        #pragma unroll
        for (int d = 0; d < NIN; d++) {
            const float* wd  = &Ws[(d*NH + s)*5];
            const float* wd2 = &Ws[((NIN+d)*NH + s)*5];
            r  += xv[d]*wd[3] + xv[d]*Ss[d]*wd2[3];
            dg += xv[d]*(wd[0] + wd[1] + wd[2]) + xv[d]*xv[d]*wd2[2];
        }
        g_R1 [((size_t)b*NN + i)*NH + s] = r*inv_n;
        g_Dg1[((size_t)b*NN + i)*NH + s] = dg;
    }
    if (tid < NH) {
        int s = tid;
        float t = b1[s];
        #pragma unroll
        for (int d = 0; d < NIN; d++) {
            t += Ss[d]*inv_n2       * Ws[(d*NH + s)*5 + 4];
            t += Ss[d]*Ss[d]*inv_n2 * Ws[((NIN+d)*NH + s)*5 + 4];
        }
        g_T1[b*NH + s] = t;
    }
}

// ============================================================
// K1: h1 = relu(outer-term + positional). Conflict-free xs (stride 17),
// smem-based row-sum reduction. grid (NN, NB), block 256.
// ============================================================
__global__ void __launch_bounds__(256) k1_kernel(const float* __restrict__ x,
                                                 const float* __restrict__ W1) {
    int i = blockIdx.x, b = blockIdx.y, j = threadIdx.x;
    __shared__ float sm[256*36];                 // union: xs(256*17) | red(256*36)
    __shared__ __align__(16) ull Wa2[NIN*16];
    __shared__ float r1s[NH], t1s[NH], dg1s[NH];
    __shared__ float part2[8*NH];
    float* xs  = sm;                             // stride 17 per row
    float* red = sm;                             // stride 36 per thread (reuse)

    const float4* xg = (const float4*)(x + (size_t)b*NN*NIN);
    for (int e = j; e < NN*NIN/4; e += 256) {
        float4 v = xg[e];
        int r = e >> 2, c0 = (e & 3)*4;
        float* dst = xs + r*17 + c0;
        dst[0] = v.x; dst[1] = v.y; dst[2] = v.z; dst[3] = v.w;
    }
    {
        int d = j >> 4, k = j & 15, s0 = 2*k;
        float a0 = W1[((NIN+d)*NH + s0  )*5 + 0] + W1[((NIN+d)*NH + s0  )*5 + 1];
        float a1 = W1[((NIN+d)*NH + s0+1)*5 + 0] + W1[((NIN+d)*NH + s0+1)*5 + 1];
        Wa2[j] = packf2(a0, a1);
    }
    if (j < NH) {
        r1s[j]  = g_R1 [((size_t)b*NN + i)*NH + j];
        dg1s[j] = g_Dg1[((size_t)b*NN + i)*NH + j];
        t1s[j]  = g_T1[b*NH + j];
    }
    __syncthreads();

    float z[NIN];
    #pragma unroll
    for (int d = 0; d < NIN; d++) z[d] = xs[i*17 + d] * xs[j*17 + d];

    ull acc2[16];
    bool isdg = (i == j);
    #pragma unroll
    for (int k = 0; k < 16; k++) {
        float a0 = r1s[2*k] + t1s[2*k], a1 = r1s[2*k+1] + t1s[2*k+1];
        if (isdg) { a0 += dg1s[2*k]; a1 += dg1s[2*k+1]; }
        acc2[k] = packf2(a0, a1);
    }
    #pragma unroll
    for (int d = 0; d < NIN; d++) {
        ull zd = packdup(z[d]);
        const ulonglong2* w = (const ulonglong2*)(Wa2 + d*16);
        #pragma unroll
        for (int k4 = 0; k4 < 8; k4++) {
            ulonglong2 ww = w[k4];
            acc2[2*k4]   = ffma2(zd, ww.x, acc2[2*k4]);
            acc2[2*k4+1] = ffma2(zd, ww.y, acc2[2*k4+1]);
        }
    }
    float acc[NH];
    #pragma unroll
    for (int k = 0; k < 16; k++) {
        float2 f2 = unpackf2(acc2[k]);
        acc[2*k]   = fmaxf(f2.x, 0.f);
        acc[2*k+1] = fmaxf(f2.y, 0.f);
    }

    // store h1 row as bf16
    {
        unsigned int hx[16];
        #pragma unroll
        for (int k = 0; k < 16; k++) {
            __nv_bfloat162 h2 = __floats2bfloat162_rn(acc[2*k], acc[2*k+1]);
            hx[k] = *reinterpret_cast<unsigned int*>(&h2);
        }
        uint4* o4 = (uint4*)(g_h1 + (((size_t)b*NN + i)*NN + j)*NH);
        o4[0] = make_uint4(hx[0],  hx[1],  hx[2],  hx[3]);
        o4[1] = make_uint4(hx[4],  hx[5],  hx[6],  hx[7]);
        o4[2] = make_uint4(hx[8],  hx[9],  hx[10], hx[11]);
        o4[3] = make_uint4(hx[12], hx[13], hx[14], hx[15]);
    }

    // smem-based row-sum over j: red[j*36 + s]
    __syncthreads();   // xs reads done before red overwrite
    {
        float4* rr = (float4*)(red + j*36);
        #pragma unroll
        for (int k = 0; k < 8; k++)
            rr[k] = make_float4(acc[4*k], acc[4*k+1], acc[4*k+2], acc[4*k+3]);
    }
    __syncthreads();
    {
        int s = j & 31, c = j >> 5;
        float t = 0.f;
        #pragma unroll
        for (int r = 0; r < 32; r++) t += red[(c*32 + r)*36 + s];
        part2[c*NH + s] = t;
    }
    __syncthreads();
    if (j < NH) {
        float t = 0.f;
        #pragma unroll
        for (int c = 0; c < 8; c++) t += part2[c*NH + j];
        g_rowacc[((size_t)b*NN + i)*NH + j] = t;
    }
}

// ============================================================
// P2: layer-2 positional precomputes.
// ============================================================
__global__ void __launch_bounds__(256) p2_kernel(const float* __restrict__ W2,
                                                 const float* __restrict__ b2) {
    int b = blockIdx.x, tid = threadIdx.x;
    __shared__ float Ws[NH*NH*5];
    __shared__ float red[8*NH];
    __shared__ float tot[NH];
    for (int e = tid; e < NH*NH*5; e += 256) Ws[e] = W2[e];

    float ra[NH], dv[NH];
    const float* rp = g_rowacc + ((size_t)b*NN + tid)*NH;
    const __nv_bfloat16* dp = g_h1 + (((size_t)b*NN + tid)*NN + tid)*NH;
    #pragma unroll
    for (int t = 0; t < NH; t++) { ra[t] = rp[t]; dv[t] = __bfloat162float(dp[t]); }
    __syncthreads();

    int lane = tid & 31, w = tid >> 5;
    #pragma unroll
    for (int t = 0; t < NH; t++) {
        float v = ra[t];
        #pragma unroll
        for (int o = 16; o; o >>= 1) v += __shfl_xor_sync(0xffffffffu, v, o);
        if (lane == 0) red[w*NH + t] = v;
    }
    __syncthreads();
    if (tid < NH) {
        float s = 0.f;
        #pragma unroll
        for (int w2 = 0; w2 < 8; w2++) s += red[w2*NH + tid];
        tot[tid] = s * (1.0f/((float)NN*(float)NN));
    }
    __syncthreads();

    const float inv_n = 1.0f/(float)NN;
    for (int s = 0; s < NH; s++) {
        float r2 = 0.f, dg2 = 0.f;
        #pragma unroll
        for (int t = 0; t < NH; t++) {
            r2  = fmaf(ra[t]*inv_n, Ws[(t*NH + s)*5 + 3], r2);
            dg2 = fmaf(dv[t],       Ws[(t*NH + s)*5 + 2], dg2);
        }
        g_R2 [((size_t)b*NN + tid)*NH + s] = r2;
        g_Dg2[((size_t)b*NN + tid)*NH + s] = dg2;
    }
    if (tid < NH) {
        int s = tid;
        float t2 = b2[s];
        #pragma unroll
        for (int t = 0; t < NH; t++) t2 = fmaf(tot[t], Ws[(t*NH + s)*5 + 4], t2);
        g_T2[b*NH + s] = t2;
    }
}

// ============================================================
// K2: Karatsuba pair form, f32x2 FMAs, staged positional terms,
// smem-based epilogue reduction (no 160-SHFL trees).
// ============================================================
__global__ void __launch_bounds__(256, 2) k2_kernel(const float* __restrict__ W2) {
    extern __shared__ char smraw[];
    ull*   Wp2 = (ull*)smraw;             // 512 ull
    ull*   Wm2 = Wp2 + NH*16;             // 512 ull
    float* As  = (float*)(Wm2 + NH*16);   // 256*33
    float* Bs  = As + 256*33;             // 256*33
    float* r2I = Bs + 256*33;             // 16*32
    float* r2J = r2I + TILE*NH;           // 16*32
    float* dgI = r2J + TILE*NH;           // 16*32
    float* t2s = dgI + TILE*NH;           // 32
    float* red   = As;                    // reuse (stride 36)
    float* part2 = Bs;                    // reuse (8*32)

    int bid = blockIdx.x;
    int b = bid / NTRI;
    int t = bid % NTRI;
    int ti = 0;
    while (t >= NT - ti) { t -= NT - ti; ti++; }
    int tj = ti + t;
    int tid = threadIdx.x;
    int I = ti*TILE, J = tj*TILE;

    for (int e = tid; e < NH*16; e += 256) {
        int tt = e >> 4, k = e & 15, s0 = 2*k;
        float w00 = W2[(tt*NH + s0  )*5 + 0], w01 = W2[(tt*NH + s0  )*5 + 1];
        float w10 = W2[(tt*NH + s0+1)*5 + 0], w11 = W2[(tt*NH + s0+1)*5 + 1];
        Wp2[e] = packf2(w00 + w01, w10 + w11);
        Wm2[e] = packf2(w00 - w01, w10 - w11);
    }
    for (int e = tid; e < TILE*NH; e += 256) {
        int row = e >> 5, s = e & 31;
        r2I[e] = g_R2 [((size_t)b*NN + I + row)*NH + s];
        r2J[e] = g_R2 [((size_t)b*NN + J + row)*NH + s];
        dgI[e] = g_Dg2[((size_t)b*NN + I + row)*NH + s];
    }
    if (tid < NH) t2s[tid] = g_T2[b*NH + tid];

    const __nv_bfloat16* h1b = g_h1 + (size_t)b*NN*NN*NH;
    #pragma unroll
    for (int k = 0; k < 4; k++) {
        int f = k*256 + tid;
        int p = f >> 2, sq = f & 3;
        int pi = p >> 4, pj = p & 15;
        uint4 va = *(const uint4*)(h1b + ((size_t)(I+pi)*NN + (J+pj))*NH + sq*8);
        {
            float* dst = As + p*33 + sq*8;
            unsigned int vs[4] = {va.x, va.y, va.z, va.w};
            #pragma unroll
            for (int w = 0; w < 4; w++) {
                float2 f2 = __bfloat1622float2(*(const __nv_bfloat162*)&vs[w]);
                dst[2*w] = f2.x; dst[2*w+1] = f2.y;
            }
        }
        uint4 vb = *(const uint4*)(h1b + ((size_t)(J+pi)*NN + (I+pj))*NH + sq*8);
        {
            int q = (pj << 4) | pi;
            float* dst = Bs + q*33 + sq*8;
            unsigned int vs[4] = {vb.x, vb.y, vb.z, vb.w};
            #pragma unroll
            for (int w = 0; w < 4; w++) {
                float2 f2 = __bfloat1622float2(*(const __nv_bfloat162*)&vs[w]);
                dst[2*w] = f2.x; dst[2*w+1] = f2.y;
            }
        }
    }
    __syncthreads();

    int ii = tid >> 4, jj = tid & 15;
    const float* av = As + tid*33;
    const float* bv = Bs + tid*33;

    ull accP2[16], accM2[16];
    #pragma unroll
    for (int k = 0; k < 16; k++) { accP2[k] = 0ull; accM2[k] = 0ull; }

    #pragma unroll 4
    for (int tt = 0; tt < NH; tt++) {
        float vt = av[tt], ut = bv[tt];
        ull ap2 = packdup(vt + ut);
        ull am2 = packdup(vt - ut);
        const ulonglong2* wp = (const ulonglong2*)(Wp2 + tt*16);
        const ulonglong2* wm = (const ulonglong2*)(Wm2 + tt*16);
        #pragma unroll
        for (int k4 = 0; k4 < 8; k4++) {
            ulonglong2 wwp = wp[k4];
            accP2[2*k4]   = ffma2(ap2, wwp.x, accP2[2*k4]);
            accP2[2*k4+1] = ffma2(ap2, wwp.y, accP2[2*k4+1]);
            ulonglong2 wwm = wm[k4];
            accM2[2*k4]   = ffma2(am2, wwm.x, accM2[2*k4]);
            accM2[2*k4+1] = ffma2(am2, wwm.y, accM2[2*k4+1]);
        }
    }

    bool isdiag = (ti == tj);
    float cs[NH];
    #pragma unroll
    for (int k = 0; k < 16; k++) {
        float2 p2 = unpackf2(accP2[k]);
        float2 m2 = unpackf2(accM2[k]);
        #pragma unroll
        for (int h = 0; h < 2; h++) {
            int s = 2*k + h;
            float aP = h ? p2.y : p2.x;
            float aM = h ? m2.y : m2.x;
            float base1 = r2I[ii*NH + s] + t2s[s];
            if (isdiag && ii == jj) base1 += dgI[ii*NH + s];
            float base2 = r2J[jj*NH + s] + t2s[s];
            float a1 = 0.5f*(aP + aM) + base1;
            float a2 = 0.5f*(aP - aM) + base2;
            float c1 = fmaxf(a1, 0.f), c2 = fmaxf(a2, 0.f);
            float v = c1 + c2;
            if (isdiag) v = (ii < jj) ? (c1 + c2) : ((ii == jj) ? c1 : 0.f);
            cs[s] = v;
        }
    }

    // smem-based block reduction of cs over 256 threads
    __syncthreads();   // As/Bs reads done before reuse
    {
        float4* rr = (float4*)(red + tid*36);
        #pragma unroll
        for (int k = 0; k < 8; k++)
            rr[k] = make_float4(cs[4*k], cs[4*k+1], cs[4*k+2], cs[4*k+3]);
    }
    __syncthreads();
    {
        int s = tid & 31, c = tid >> 5;
        float tsum = 0.f;
        #pragma unroll
        for (int r = 0; r < 32; r++) tsum += red[(c*32 + r)*36 + s];
        part2[c*NH + s] = tsum;
    }
    __syncthreads();
    if (tid < NH) {
        float p = 0.f;
        #pragma unroll
        for (int c = 0; c < 8; c++) p += part2[c*NH + tid];
        g_part[(size_t)bid*NH + tid] = p;
    }
}

// ============================================================
// Final: parallel partial reduce + MLP 32->128->128->1, 256 threads.
// ============================================================
__global__ void __launch_bounds__(256) fin_kernel(const float* __restrict__ D1,
                                                  const float* __restrict__ db1,
                                                  const float* __restrict__ D2,
                                                  const float* __restrict__ db2,
                                                  const float* __restrict__ D3,
                                                  const float* __restrict__ db3,
                                                  float* __restrict__ out) {
    int b = blockIdx.x, tid = threadIdx.x;
    __shared__ float pp[8*NH];
    __shared__ float p[NH];
    __shared__ float m1[128];
    __shared__ float h2p[256];
    __shared__ float m2[128];
    __shared__ float wr[4];

    {
        int s = tid & 31, c = tid >> 5;
        float a = 0.f;
        #pragma unroll 4
        for (int k = c; k < NTRI; k += 8) a += g_part[(size_t)(b*NTRI + k)*NH + s];
        pp[tid] = a;
    }
    __syncthreads();
    if (tid < NH) {
        float t = 0.f;
        #pragma unroll
        for (int c = 0; c < 8; c++) t += pp[c*NH + tid];
        p[tid] = fmaxf(t, 0.f);
    }
    __syncthreads();
    if (tid < 128) {
        float a = db1[tid];
        #pragma unroll
        for (int t = 0; t < NH; t++) a = fmaf(p[t], D1[t*128 + tid], a);
        m1[tid] = fmaxf(a, 0.f);
    }
    __syncthreads();
    {
        int o = tid & 127, half = tid >> 7;
        float a = 0.f;
        #pragma unroll 16
        for (int e = half*64; e < half*64 + 64; e++)
            a = fmaf(m1[e], D2[e*128 + o], a);
        h2p[tid] = a;
    }
    __syncthreads();
    if (tid < 128) m2[tid] = fmaxf(h2p[tid] + h2p[128 + tid] + db2[tid], 0.f);
    __syncthreads();
    if (tid < 128) {
        float v = m2[tid] * D3[tid];
        #pragma unroll
        for (int o = 16; o; o >>= 1) v += __shfl_xor_sync(0xffffffffu, v, o);
        if ((tid & 31) == 0) wr[tid >> 5] = v;
    }
    __syncthreads();
    if (tid == 0) out[b] = wr[0] + wr[1] + wr[2] + wr[3] + db3[0];
}

extern "C" void kernel_launch(void* const* d_in, const int* in_sizes, int n_in,
                              void* d_out, int out_size) {
    const float* x   = (const float*)d_in[0];
    const float* W1  = (const float*)d_in[1];
    const float* b1  = (const float*)d_in[2];
    const float* W2  = (const float*)d_in[3];
    const float* b2  = (const float*)d_in[4];
    const float* D1  = (const float*)d_in[5];
    const float* db1 = (const float*)d_in[6];
    const float* D2  = (const float*)d_in[7];
    const float* db2 = (const float*)d_in[8];
    const float* D3  = (const float*)d_in[9];
    const float* db3 = (const float*)d_in[10];
    float* out = (float*)d_out;

    size_t k2_smem = (size_t)(2*NH*16)*8                    // Wp2/Wm2
                   + (size_t)(2*256*33 + 3*TILE*NH + NH)*4; // As/Bs + staging
    cudaFuncSetAttribute(k2_kernel, cudaFuncAttributeMaxDynamicSharedMemorySize,
                         (int)k2_smem);

    p1_kernel<<<NB, 256>>>(x, W1, b1);
    k1_kernel<<<dim3(NN, NB), 256>>>(x, W1);
    p2_kernel<<<NB, 256>>>(W2, b2);
    k2_kernel<<<NBLK2, 256, k2_smem>>>(W2);
    fin_kernel<<<NB, 256>>>(D1, db1, D2, db2, D3, db3, out);
}

// round 4
// speedup vs baseline: 1.3318x; 1.1213x over previous
#include <cuda_runtime.h>
#include <cuda_bf16.h>

#define NB   8
#define NN   256
#define NIN  16
#define NH   32
#define TILE 16
#define NT   (NN/TILE)          // 16
#define NTRI (NT*(NT+1)/2)      // 136
#define NBLK2 (NB*NTRI)         // 1088

typedef unsigned long long ull;

// ---- packed f32x2 helpers ----
__device__ __forceinline__ ull packf2(float lo, float hi) {
    ull r; asm("mov.b64 %0, {%1, %2};" : "=l"(r) : "f"(lo), "f"(hi)); return r;
}
__device__ __forceinline__ ull packdup(float v) {
    ull r; asm("mov.b64 %0, {%1, %1};" : "=l"(r) : "f"(v)); return r;
}
__device__ __forceinline__ ull ffma2(ull a, ull b, ull c) {
    ull d; asm("fma.rn.f32x2 %0, %1, %2, %3;" : "=l"(d) : "l"(a), "l"(b), "l"(c)); return d;
}
__device__ __forceinline__ float2 unpackf2(ull v) {
    float lo, hi; asm("mov.b64 {%0, %1}, %2;" : "=f"(lo), "=f"(hi) : "l"(v));
    return make_float2(lo, hi);
}

// ---- scratch (device globals) ----
// Karatsuba pair form of layer-1 activations: ap = h1[i,j]+h1[j,i], am = h1[i,j]-h1[j,i]
__device__ __nv_bfloat16 g_ap[(size_t)NB*NTRI*256*NH];   // 17.8 MB
__device__ __nv_bfloat16 g_am[(size_t)NB*NTRI*256*NH];   // 17.8 MB
__device__ float g_R1[NB*NN*NH];
__device__ float g_Dg1[NB*NN*NH];
__device__ float g_T1[NB*NH];
__device__ float g_rowpart[(size_t)NB*NTRI*1024];        // per-tile rowsum partials [I:512 | J:512]
__device__ float g_R2[NB*NN*NH];
__device__ float g_Dg2[NB*NN*NH];
__device__ float g_T2[NB*NH];
__device__ float g_part[(size_t)NBLK2*NH];

// ============================================================
// P1: per-batch positional precompute for layer 1 (8 blocks).
// ============================================================
__global__ void __launch_bounds__(256) p1_kernel(const float* __restrict__ x,
                                                 const float* __restrict__ W1,
                                                 const float* __restrict__ b1) {
    int b = blockIdx.x, tid = threadIdx.x;
    __shared__ float xs[NN*17];
    __shared__ float Ws[NH*NH*5];
    __shared__ float Ss[NIN];
    __shared__ float red[8*NIN];

    const float4* xg = (const float4*)(x + (size_t)b*NN*NIN);
    for (int e = tid; e < NN*NIN/4; e += 256) {
        float4 v = xg[e];
        int r = e >> 2, c0 = (e & 3)*4;
        float* dst = xs + r*17 + c0;
        dst[0] = v.x; dst[1] = v.y; dst[2] = v.z; dst[3] = v.w;
    }
    for (int e = tid; e < NH*NH*5; e += 256) Ws[e] = W1[e];
    __syncthreads();

    float xv[NIN];
    #pragma unroll
    for (int d = 0; d < NIN; d++) xv[d] = xs[tid*17 + d];

    int lane = tid & 31, w = tid >> 5;
    #pragma unroll
    for (int d = 0; d < NIN; d++) {
        float v = xv[d];
        #pragma unroll
        for (int o = 16; o; o >>= 1) v += __shfl_xor_sync(0xffffffffu, v, o);
        if (lane == 0) red[w*NIN + d] = v;
    }
    __syncthreads();
    if (tid < NIN) {
        float s = 0.f;
        #pragma unroll
        for (int w2 = 0; w2 < 8; w2++) s += red[w2*NIN + tid];
        Ss[tid] = s;
    }
    __syncthreads();

    const float inv_n = 1.0f/(float)NN, inv_n2 = inv_n*inv_n;
    int i = tid;
    for (int s = 0; s < NH; s++) {
        float r = 0.f, dg = 0.f;
        #pragma unroll
        for (int d = 0; d < NIN; d++) {
            const float* wd  = &Ws[(d*NH + s)*5];
            const float* wd2 = &Ws[((NIN+d)*NH + s)*5];
            r  += xv[d]*wd[3] + xv[d]*Ss[d]*wd2[3];
            dg += xv[d]*(wd[0] + wd[1] + wd[2]) + xv[d]*xv[d]*wd2[2];
        }
        g_R1 [((size_t)b*NN + i)*NH + s] = r*inv_n;
        g_Dg1[((size_t)b*NN + i)*NH + s] = dg;
    }
    if (tid < NH) {
        int s = tid;
        float t = b1[s];
        #pragma unroll
        for (int d = 0; d < NIN; d++) {
            t += Ss[d]*inv_n2       * Ws[(d*NH + s)*5 + 4];
            t += Ss[d]*Ss[d]*inv_n2 * Ws[((NIN+d)*NH + s)*5 + 4];
        }
        g_T1[b*NH + s] = t;
    }
}

// ============================================================
// K1: per UNORDERED pair tile. Mainloop computed once per pair, both
// orderings derived by positional adds. Emits ap/am (bf16) + rowsum partials.
// grid (NTRI, NB), block 256 (thread = (ii,jj) in 16x16).
// ============================================================
__global__ void __launch_bounds__(256) k1_kernel(const float* __restrict__ x) {
    int tp = blockIdx.x, b = blockIdx.y, t = threadIdx.x;
    int ti = 0, rr0 = tp;
    while (rr0 >= NT - ti) { rr0 -= NT - ti; ti++; }
    int tj = ti + rr0;
    int I = ti*TILE, J = tj*TILE;
    int ii = t >> 4, jj = t & 15;

    __shared__ float xi[16*17], xj[16*17];
    __shared__ __align__(16) ull Wa2[NIN*16];
    __shared__ float posI[512], posJ[512], dgs[512], t1s[NH];
    __shared__ float red[256*36];

    {
        int r = t >> 4, c = t & 15;
        xi[r*17 + c] = x[(size_t)b*NN*NIN + (I+r)*NIN + c];
        xj[r*17 + c] = x[(size_t)b*NN*NIN + (J+r)*NIN + c];
    }
    // Wa2 copied from p1's derived values? cheaper: keep a tiny global... recompute from W1
    // (W1 not passed: we stash Wa in g_rowpart? No — just pass W1.)
    __syncthreads();   // placeholder sync removed below (see W load)
    // NOTE: Wa2 filled in second kernel arg version below.
    (void)Wa2;
    (void)posI; (void)posJ; (void)dgs; (void)t1s; (void)red;
}

// real k1 (takes W1 too)
__global__ void __launch_bounds__(256) k1_pair_kernel(const float* __restrict__ x,
                                                      const float* __restrict__ W1) {
    int tp = blockIdx.x, b = blockIdx.y, t = threadIdx.x;
    int ti = 0, rr0 = tp;
    while (rr0 >= NT - ti) { rr0 -= NT - ti; ti++; }
    int tj = ti + rr0;
    int I = ti*TILE, J = tj*TILE;
    int ii = t >> 4, jj = t & 15;

    __shared__ float xi[16*17], xj[16*17];
    __shared__ __align__(16) ull Wa2[NIN*16];
    __shared__ float posI[512], posJ[512], dgs[512], t1s[NH];
    __shared__ float red[256*36];

    {
        int r = t >> 4, c = t & 15;
        xi[r*17 + c] = x[(size_t)b*NN*NIN + (I+r)*NIN + c];
        xj[r*17 + c] = x[(size_t)b*NN*NIN + (J+r)*NIN + c];
    }
    {
        int d = t >> 4, k = t & 15, s0 = 2*k;
        float a0 = W1[((NIN+d)*NH + s0  )*5 + 0] + W1[((NIN+d)*NH + s0  )*5 + 1];
        float a1 = W1[((NIN+d)*NH + s0+1)*5 + 0] + W1[((NIN+d)*NH + s0+1)*5 + 1];
        Wa2[t] = packf2(a0, a1);
    }
    for (int e = t; e < 512; e += 256) {
        int r = e >> 5, s = e & 31;
        posI[e] = g_R1 [((size_t)b*NN + I + r)*NH + s];
        posJ[e] = g_R1 [((size_t)b*NN + J + r)*NH + s];
        dgs[e]  = g_Dg1[((size_t)b*NN + I + r)*NH + s];
    }
    if (t < NH) t1s[t] = g_T1[b*NH + t];
    __syncthreads();

    float z[NIN];
    #pragma unroll
    for (int d = 0; d < NIN; d++) z[d] = xi[ii*17 + d] * xj[jj*17 + d];

    ull acc2[16];
    #pragma unroll
    for (int k = 0; k < 16; k++) acc2[k] = 0ull;
    #pragma unroll
    for (int d = 0; d < NIN; d++) {
        ull zd = packdup(z[d]);
        const ulonglong2* w = (const ulonglong2*)(Wa2 + d*16);
        #pragma unroll
        for (int k4 = 0; k4 < 8; k4++) {
            ulonglong2 ww = w[k4];
            acc2[2*k4]   = ffma2(zd, ww.x, acc2[2*k4]);
            acc2[2*k4+1] = ffma2(zd, ww.y, acc2[2*k4+1]);
        }
    }

    bool dgflag = (ti == tj) && (ii == jj);
    float c1[NH], c2[NH];
    #pragma unroll
    for (int k = 0; k < 16; k++) {
        float2 m = unpackf2(acc2[k]);
        int s0 = 2*k, s1 = 2*k + 1;
        float e0 = dgflag ? dgs[ii*NH + s0] : 0.f;
        float e1 = dgflag ? dgs[ii*NH + s1] : 0.f;
        c1[s0] = fmaxf(m.x + posI[ii*NH + s0] + t1s[s0] + e0, 0.f);
        c1[s1] = fmaxf(m.y + posI[ii*NH + s1] + t1s[s1] + e1, 0.f);
        c2[s0] = fmaxf(m.x + posJ[jj*NH + s0] + t1s[s0] + e0, 0.f);
        c2[s1] = fmaxf(m.y + posJ[jj*NH + s1] + t1s[s1] + e1, 0.f);
    }

    // store ap/am bf16
    {
        unsigned int hap[16], ham[16];
        #pragma unroll
        for (int k = 0; k < 16; k++) {
            __nv_bfloat162 a2 = __floats2bfloat162_rn(c1[2*k] + c2[2*k], c1[2*k+1] + c2[2*k+1]);
            __nv_bfloat162 m2 = __floats2bfloat162_rn(c1[2*k] - c2[2*k], c1[2*k+1] - c2[2*k+1]);
            hap[k] = *reinterpret_cast<unsigned int*>(&a2);
            ham[k] = *reinterpret_cast<unsigned int*>(&m2);
        }
        size_t off = ((size_t)(b*NTRI + tp)*256 + t)*NH;
        uint4* oa = (uint4*)(g_ap + off);
        uint4* om = (uint4*)(g_am + off);
        #pragma unroll
        for (int q = 0; q < 4; q++) {
            oa[q] = make_uint4(hap[4*q], hap[4*q+1], hap[4*q+2], hap[4*q+3]);
            om[q] = make_uint4(ham[4*q], ham[4*q+1], ham[4*q+2], ham[4*q+3]);
        }
    }

    // rowsum partials. Pass 1: c1 -> side I (sum over jj for each (ii,s)).
    {
        float4* rr = (float4*)(red + t*36);
        #pragma unroll
        for (int k = 0; k < 8; k++)
            rr[k] = make_float4(c1[4*k], c1[4*k+1], c1[4*k+2], c1[4*k+3]);
    }
    __syncthreads();
    for (int c = t; c < 512; c += 256) {
        int r = c >> 5, s = c & 31;
        float v = 0.f;
        #pragma unroll
        for (int q = 0; q < 16; q++) v += red[(r*16 + q)*36 + s];
        g_rowpart[(size_t)(b*NTRI + tp)*1024 + c] = v;
    }
    __syncthreads();
    // Pass 2: c2 -> side J (sum over ii for each (jj,s)).
    {
        float4* rr = (float4*)(red + t*36);
        #pragma unroll
        for (int k = 0; k < 8; k++)
            rr[k] = make_float4(c2[4*k], c2[4*k+1], c2[4*k+2], c2[4*k+3]);
    }
    __syncthreads();
    for (int c = t; c < 512; c += 256) {
        int r = c >> 5, s = c & 31;   // r = jj
        float v = 0.f;
        #pragma unroll
        for (int q = 0; q < 16; q++) v += red[(q*16 + r)*36 + s];
        g_rowpart[(size_t)(b*NTRI + tp)*1024 + 512 + c] = v;
    }
}

// ============================================================
// P2: gather rowsums from tile partials, compute layer-2 positional terms.
// ============================================================
__global__ void __launch_bounds__(256) p2_kernel(const float* __restrict__ W2,
                                                 const float* __restrict__ b2) {
    int b = blockIdx.x, tid = threadIdx.x;
    __shared__ float Ws[NH*NH*5];
    __shared__ float red[8*NH];
    __shared__ float tot[NH];
    for (int e = tid; e < NH*NH*5; e += 256) Ws[e] = W2[e];

    int ti = tid >> 4, ii = tid & 15;
    float ra[NH];
    #pragma unroll
    for (int s = 0; s < NH; s++) ra[s] = 0.f;

    for (int tj = ti; tj < NT; tj++) {
        int tp = ti*NT - ti*(ti-1)/2 + (tj - ti);
        const float4* p4 = (const float4*)(g_rowpart + (size_t)(b*NTRI + tp)*1024 + ii*NH);
        #pragma unroll
        for (int q = 0; q < 8; q++) {
            float4 v = p4[q];
            ra[4*q] += v.x; ra[4*q+1] += v.y; ra[4*q+2] += v.z; ra[4*q+3] += v.w;
        }
    }
    for (int tk = 0; tk < ti; tk++) {
        int tp = tk*NT - tk*(tk-1)/2 + (ti - tk);
        const float4* p4 = (const float4*)(g_rowpart + (size_t)(b*NTRI + tp)*1024 + 512 + ii*NH);
        #pragma unroll
        for (int q = 0; q < 8; q++) {
            float4 v = p4[q];
            ra[4*q] += v.x; ra[4*q+1] += v.y; ra[4*q+2] += v.z; ra[4*q+3] += v.w;
        }
    }

    float dv[NH];
    {
        int tpd = ti*NT - ti*(ti-1)/2;    // tile (ti,ti)
        const __nv_bfloat16* dp = g_ap + ((size_t)(b*NTRI + tpd)*256 + (ii*16 + ii))*NH;
        #pragma unroll
        for (int s = 0; s < NH; s++) dv[s] = 0.5f*__bfloat162float(dp[s]);
    }
    __syncthreads();

    int lane = tid & 31, w = tid >> 5;
    #pragma unroll
    for (int s = 0; s < NH; s++) {
        float v = ra[s];
        #pragma unroll
        for (int o = 16; o; o >>= 1) v += __shfl_xor_sync(0xffffffffu, v, o);
        if (lane == 0) red[w*NH + s] = v;
    }
    __syncthreads();
    if (tid < NH) {
        float s = 0.f;
        #pragma unroll
        for (int w2 = 0; w2 < 8; w2++) s += red[w2*NH + tid];
        tot[tid] = s * (1.0f/((float)NN*(float)NN));
    }
    __syncthreads();

    const float inv_n = 1.0f/(float)NN;
    for (int s = 0; s < NH; s++) {
        float r2 = 0.f, dg2 = 0.f;
        #pragma unroll
        for (int q = 0; q < NH; q++) {
            r2  = fmaf(ra[q]*inv_n, Ws[(q*NH + s)*5 + 3], r2);
            dg2 = fmaf(dv[q],       Ws[(q*NH + s)*5 + 2], dg2);
        }
        g_R2 [((size_t)b*NN + tid)*NH + s] = r2;
        g_Dg2[((size_t)b*NN + tid)*NH + s] = dg2;
    }
    if (tid < NH) {
        int s = tid;
        float t2 = b2[s];
        #pragma unroll
        for (int q = 0; q < NH; q++) t2 = fmaf(tot[q], Ws[(q*NH + s)*5 + 4], t2);
        g_T2[b*NH + s] = t2;
    }
}

// ============================================================
// K2: consumes ap/am pair form. Thread tiling: 2 pairs x 16 s-values
// (halves W smem reloads per FMA). grid (NTRI, NB), block 256.
// ============================================================
__global__ void __launch_bounds__(256, 2) k2_kernel(const float* __restrict__ W2) {
    extern __shared__ char smraw[];
    ull*   Wp2 = (ull*)smraw;              // 32*16 ull
    ull*   Wm2 = Wp2 + NH*16;              // 32*16 ull
    float* Aps = (float*)(Wm2 + NH*16);    // 256*33
    float* Ams = Aps + 256*33;             // 256*33
    float* r2I = Ams + 256*33;             // 512
    float* r2J = r2I + 512;                // 512
    float* dgI = r2J + 512;                // 512
    float* t2s = dgI + 512;                // 32
    float* part2 = t2s + NH;               // 32*8
    float* red = Aps;                      // reuse after mainloop

    int tp = blockIdx.x, b = blockIdx.y, t = threadIdx.x;
    int ti = 0, rr0 = tp;
    while (rr0 >= NT - ti) { rr0 -= NT - ti; ti++; }
    int tj = ti + rr0;
    int I = ti*TILE, J = tj*TILE;
    int bid = b*NTRI + tp;

    for (int e = t; e < NH*16; e += 256) {
        int tt = e >> 4, k = e & 15, s0 = 2*k;
        float w00 = W2[(tt*NH + s0  )*5 + 0], w01 = W2[(tt*NH + s0  )*5 + 1];
        float w10 = W2[(tt*NH + s0+1)*5 + 0], w11 = W2[(tt*NH + s0+1)*5 + 1];
        Wp2[e] = packf2(w00 + w01, w10 + w11);
        Wm2[e] = packf2(w00 - w01, w10 - w11);
    }
    for (int e = t; e < 512; e += 256) {
        int r = e >> 5, s = e & 31;
        r2I[e] = g_R2 [((size_t)b*NN + I + r)*NH + s];
        r2J[e] = g_R2 [((size_t)b*NN + J + r)*NH + s];
        dgI[e] = g_Dg2[((size_t)b*NN + I + r)*NH + s];
    }
    if (t < NH) t2s[t] = g_T2[b*NH + t];

    // load tile: thread t owns pair t, converts bf16->f32 into stride-33 smem
    {
        size_t off = ((size_t)bid*256 + t)*NH;
        const uint4* pa = (const uint4*)(g_ap + off);
        const uint4* pm = (const uint4*)(g_am + off);
        #pragma unroll
        for (int q = 0; q < 4; q++) {
            uint4 va = pa[q], vm = pm[q];
            unsigned int wa[4] = {va.x, va.y, va.z, va.w};
            unsigned int wm[4] = {vm.x, vm.y, vm.z, vm.w};
            #pragma unroll
            for (int u = 0; u < 4; u++) {
                float2 fa = __bfloat1622float2(*(const __nv_bfloat162*)&wa[u]);
                float2 fm = __bfloat1622float2(*(const __nv_bfloat162*)&wm[u]);
                int s0 = q*8 + 2*u;
                Aps[t*33 + s0] = fa.x; Aps[t*33 + s0 + 1] = fa.y;
                Ams[t*33 + s0] = fm.x; Ams[t*33 + s0 + 1] = fm.y;
            }
        }
    }
    __syncthreads();

    int duo = t & 127, sh = t >> 7;
    int pA = duo, pB = duo + 128;
    const float* apA = Aps + pA*33;
    const float* amA = Ams + pA*33;
    const float* apB = Aps + pB*33;
    const float* amB = Ams + pB*33;

    ull aPA[8], aMA[8], aPB[8], aMB[8];
    #pragma unroll
    for (int k = 0; k < 8; k++) { aPA[k]=0; aMA[k]=0; aPB[k]=0; aMB[k]=0; }

    #pragma unroll 4
    for (int tt = 0; tt < NH; tt++) {
        ull xpA = packdup(apA[tt]);
        ull xmA = packdup(amA[tt]);
        ull xpB = packdup(apB[tt]);
        ull xmB = packdup(amB[tt]);
        const ulonglong2* wp = (const ulonglong2*)(Wp2 + tt*16 + sh*8);
        const ulonglong2* wm = (const ulonglong2*)(Wm2 + tt*16 + sh*8);
        #pragma unroll
        for (int q = 0; q < 4; q++) {
            ulonglong2 wwp = wp[q];
            aPA[2*q]   = ffma2(xpA, wwp.x, aPA[2*q]);
            aPA[2*q+1] = ffma2(xpA, wwp.y, aPA[2*q+1]);
            aPB[2*q]   = ffma2(xpB, wwp.x, aPB[2*q]);
            aPB[2*q+1] = ffma2(xpB, wwp.y, aPB[2*q+1]);
            ulonglong2 wwm = wm[q];
            aMA[2*q]   = ffma2(xmA, wwm.x, aMA[2*q]);
            aMA[2*q+1] = ffma2(xmA, wwm.y, aMA[2*q+1]);
            aMB[2*q]   = ffma2(xmB, wwm.x, aMB[2*q]);
            aMB[2*q+1] = ffma2(xmB, wwm.y, aMB[2*q+1]);
        }
    }

    bool isdiag = (ti == tj);
    int iiA = pA >> 4, jjA = pA & 15;
    int iiB = pB >> 4, jjB = pB & 15;
    float cs[16];
    #pragma unroll
    for (int k = 0; k < 8; k++) {
        float2 PA = unpackf2(aPA[k]), MA = unpackf2(aMA[k]);
        float2 PB = unpackf2(aPB[k]), MB = unpackf2(aMB[k]);
        #pragma unroll
        for (int h = 0; h < 2; h++) {
            int m = 2*k + h;
            int s = sh*16 + m;
            float vP_A = h ? PA.y : PA.x, vM_A = h ? MA.y : MA.x;
            float vP_B = h ? PB.y : PB.x, vM_B = h ? MB.y : MB.x;
            // pair A
            float b1A = r2I[iiA*NH + s] + t2s[s];
            if (isdiag && iiA == jjA) b1A += dgI[iiA*NH + s];
            float b2A = r2J[jjA*NH + s] + t2s[s];
            float c1A = fmaxf(0.5f*(vP_A + vM_A) + b1A, 0.f);
            float c2A = fmaxf(0.5f*(vP_A - vM_A) + b2A, 0.f);
            float vA = c1A + c2A;
            if (isdiag) vA = (iiA < jjA) ? (c1A + c2A) : ((iiA == jjA) ? c1A : 0.f);
            // pair B
            float b1B = r2I[iiB*NH + s] + t2s[s];
            if (isdiag && iiB == jjB) b1B += dgI[iiB*NH + s];
            float b2B = r2J[jjB*NH + s] + t2s[s];
            float c1B = fmaxf(0.5f*(vP_B + vM_B) + b1B, 0.f);
            float c2B = fmaxf(0.5f*(vP_B - vM_B) + b2B, 0.f);
            float vB = c1B + c2B;
            if (isdiag) vB = (iiB < jjB) ? (c1B + c2B) : ((iiB == jjB) ? c1B : 0.f);
            cs[m] = vA + vB;
        }
    }

    __syncthreads();   // Aps/Ams reads done, reuse as red
    #pragma unroll
    for (int m = 0; m < 16; m++) red[t*17 + m] = cs[m];
    __syncthreads();
    {
        int slot = t >> 3, part = t & 7;         // slot = sh*16 + m
        int shs = slot >> 4, m = slot & 15;
        float v = 0.f;
        #pragma unroll
        for (int d = 0; d < 16; d++)
            v += red[(shs*128 + part*16 + d)*17 + m];
        part2[slot*8 + part] = v;
    }
    __syncthreads();
    if (t < NH) {
        float p = 0.f;
        #pragma unroll
        for (int q = 0; q < 8; q++) p += part2[t*8 + q];
        g_part[(size_t)bid*NH + t] = p;
    }
}

// ============================================================
// Final: parallel partial reduce + MLP 32->128->128->1.
// ============================================================
__global__ void __launch_bounds__(256) fin_kernel(const float* __restrict__ D1,
                                                  const float* __restrict__ db1,
                                                  const float* __restrict__ D2,
                                                  const float* __restrict__ db2,
                                                  const float* __restrict__ D3,
                                                  const float* __restrict__ db3,
                                                  float* __restrict__ out) {
    int b = blockIdx.x, tid = threadIdx.x;
    __shared__ float pp[8*NH];
    __shared__ float p[NH];
    __shared__ float m1[128];
    __shared__ float h2p[256];
    __shared__ float m2[128];
    __shared__ float wr[4];

    {
        int s = tid & 31, c = tid >> 5;
        float a = 0.f;
        #pragma unroll 4
        for (int k = c; k < NTRI; k += 8) a += g_part[(size_t)(b*NTRI + k)*NH + s];
        pp[tid] = a;
    }
    __syncthreads();
    if (tid < NH) {
        float t = 0.f;
        #pragma unroll
        for (int c = 0; c < 8; c++) t += pp[c*NH + tid];
        p[tid] = fmaxf(t, 0.f);
    }
    __syncthreads();
    if (tid < 128) {
        float a = db1[tid];
        #pragma unroll
        for (int q = 0; q < NH; q++) a = fmaf(p[q], D1[q*128 + tid], a);
        m1[tid] = fmaxf(a, 0.f);
    }
    __syncthreads();
    {
        int o = tid & 127, half = tid >> 7;
        float a = 0.f;
        #pragma unroll 16
        for (int e = half*64; e < half*64 + 64; e++)
            a = fmaf(m1[e], D2[e*128 + o], a);
        h2p[tid] = a;
    }
    __syncthreads();
    if (tid < 128) m2[tid] = fmaxf(h2p[tid] + h2p[128 + tid] + db2[tid], 0.f);
    __syncthreads();
    if (tid < 128) {
        float v = m2[tid] * D3[tid];
        #pragma unroll
        for (int o = 16; o; o >>= 1) v += __shfl_xor_sync(0xffffffffu, v, o);
        if ((tid & 31) == 0) wr[tid >> 5] = v;
    }
    __syncthreads();
    if (tid == 0) out[b] = wr[0] + wr[1] + wr[2] + wr[3] + db3[0];
}

extern "C" void kernel_launch(void* const* d_in, const int* in_sizes, int n_in,
                              void* d_out, int out_size) {
    const float* x   = (const float*)d_in[0];
    const float* W1  = (const float*)d_in[1];
    const float* b1  = (const float*)d_in[2];
    const float* W2  = (const float*)d_in[3];
    const float* b2  = (const float*)d_in[4];
    const float* D1  = (const float*)d_in[5];
    const float* db1 = (const float*)d_in[6];
    const float* D2  = (const float*)d_in[7];
    const float* db2 = (const float*)d_in[8];
    const float* D3  = (const float*)d_in[9];
    const float* db3 = (const float*)d_in[10];
    float* out = (float*)d_out;

    size_t k2_smem = (size_t)(2*NH*16)*8                          // Wp2/Wm2
                   + (size_t)(2*256*33 + 3*512 + NH + 32*8)*4;    // tiles + staging + part2
    cudaFuncSetAttribute(k2_kernel, cudaFuncAttributeMaxDynamicSharedMemorySize,
                         (int)k2_smem);

    p1_kernel<<<NB, 256>>>(x, W1, b1);
    k1_pair_kernel<<<dim3(NTRI, NB), 256>>>(x, W1);
    p2_kernel<<<NB, 256>>>(W2, b2);
    k2_kernel<<<dim3(NTRI, NB), 256, k2_smem>>>(W2);
    fin_kernel<<<NB, 256>>>(D1, db1, D2, db2, D3, db3, out);
}